// round 1
// baseline (speedup 1.0000x reference)
#include <cuda_runtime.h>
#include <cuda_bf16.h>
#include <cstdint>

typedef __nv_bfloat16 bf16;

// ---------------- problem dims (fixed by setup_inputs) ----------------
#define CH     256        // channels
#define NHEAD  8
#define HDIM   32
#define HSZ    128
#define WSZ    128
#define LTOK   16384      // H*W
#define NWIN   256        // windows per image
#define WTOK   64         // tokens per window
#define BMAX   8
#define HID    1024
#define SSHIFT 4
#define SCL    0.17677669529663687f   // 1/sqrt(32)

#define MROWS_MAX (BMAX*LTOK)

// ---------------- scratch (device globals; no allocation allowed) ----
__device__ bf16  g_rw[(size_t)MROWS_MAX*CH];
__device__ bf16  g_aw[(size_t)MROWS_MAX*CH];
__device__ bf16  g_q [(size_t)MROWS_MAX*CH];
__device__ bf16  g_kv[(size_t)MROWS_MAX*2*CH];
__device__ bf16  g_ao[(size_t)MROWS_MAX*CH];
__device__ float g_x [(size_t)MROWS_MAX*CH];
__device__ bf16  g_xn[(size_t)MROWS_MAX*CH];
__device__ bf16  g_h1[(size_t)MROWS_MAX*HID];
__device__ bf16  g_wq [CH*CH];
__device__ bf16  g_wkv[CH*2*CH];
__device__ bf16  g_wp [CH*CH];
__device__ bf16  g_w1 [CH*HID];
__device__ bf16  g_w2 [HID*CH];

// ---------------- helpers ----------------
__device__ __forceinline__ void mma16816(float* d, const uint32_t* a, const uint32_t* b) {
    asm volatile(
        "mma.sync.aligned.m16n8k16.row.col.f32.bf16.bf16.f32 "
        "{%0,%1,%2,%3}, {%4,%5,%6,%7}, {%8,%9}, {%0,%1,%2,%3};\n"
        : "+f"(d[0]), "+f"(d[1]), "+f"(d[2]), "+f"(d[3])
        : "r"(a[0]), "r"(a[1]), "r"(a[2]), "r"(a[3]), "r"(b[0]), "r"(b[1]));
}

__device__ __forceinline__ uint32_t pack_bf16(float x, float y) {
    __nv_bfloat162 t = __floats2bfloat162_rn(x, y);   // x -> low half
    return *reinterpret_cast<uint32_t*>(&t);
}

// windowed row -> original (b,l) row  (win-reverse + roll(+SS))
__device__ __forceinline__ int winrow_to_orig(int r) {
    int b = r >> 14;            // / 16384
    int rem = r & 16383;
    int win = rem >> 6, n = rem & 63;
    int wh = win >> 4, ww = win & 15;
    int ih = n >> 3,  iw = n & 7;
    int h0 = (wh*8 + ih + SSHIFT) & (HSZ-1);
    int w0 = (ww*8 + iw + SSHIFT) & (WSZ-1);
    return (b << 14) + (h0 << 7) + w0;
}

// ---------------- weight fp32 -> bf16 conversion ----------------
__global__ void cvt_weights_k(const float* __restrict__ qw, const float* __restrict__ kvw,
                              const float* __restrict__ pw, const float* __restrict__ w1,
                              const float* __restrict__ w2) {
    int i = blockIdx.x * 256 + threadIdx.x;
    if (i < CH*CH)    g_wq[i]  = __float2bfloat16(qw[i]);
    if (i < CH*2*CH)  g_wkv[i] = __float2bfloat16(kvw[i]);
    if (i < CH*CH)    g_wp[i]  = __float2bfloat16(pw[i]);
    if (i < CH*HID)   g_w1[i]  = __float2bfloat16(w1[i]);
    if (i < HID*CH)   g_w2[i]  = __float2bfloat16(w2[i]);
}

// ---------------- LayerNorm (+ optional shift/window gather) ----------
// one warp per destination row; processes one or two tensors
__global__ void ln_k(const float* __restrict__ in0, const float* __restrict__ in1,
                     const float* __restrict__ gam, const float* __restrict__ bet,
                     bf16* __restrict__ out0, bf16* __restrict__ out1,
                     int nrows, int gather) {
    int gw = (blockIdx.x * blockDim.x + threadIdx.x) >> 5;
    if (gw >= nrows) return;
    int lane = threadIdx.x & 31;

    size_t src;
    if (gather) src = (size_t)winrow_to_orig(gw) * CH;
    else        src = (size_t)gw * CH;
    size_t dst = (size_t)gw * CH;

    float4 gg0 = *(const float4*)(gam + lane*8);
    float4 gg1 = *(const float4*)(gam + lane*8 + 4);
    float4 bb0 = *(const float4*)(bet + lane*8);
    float4 bb1 = *(const float4*)(bet + lane*8 + 4);

    for (int t = 0; t < 2; t++) {
        const float* in  = (t == 0) ? in0  : in1;
        bf16*        out = (t == 0) ? out0 : out1;
        if (in == nullptr) break;

        float4 v0 = *(const float4*)(in + src + lane*8);
        float4 v1 = *(const float4*)(in + src + lane*8 + 4);
        float s  = v0.x+v0.y+v0.z+v0.w + v1.x+v1.y+v1.z+v1.w;
        float q  = v0.x*v0.x+v0.y*v0.y+v0.z*v0.z+v0.w*v0.w
                 + v1.x*v1.x+v1.y*v1.y+v1.z*v1.z+v1.w*v1.w;
        #pragma unroll
        for (int o = 16; o; o >>= 1) {
            s += __shfl_xor_sync(0xffffffffu, s, o);
            q += __shfl_xor_sync(0xffffffffu, q, o);
        }
        float mean = s * (1.f/CH);
        float var  = q * (1.f/CH) - mean*mean;
        float inv  = rsqrtf(var + 1e-5f);

        __nv_bfloat162* op = (__nv_bfloat162*)(out + dst + lane*8);
        op[0] = __floats2bfloat162_rn((v0.x-mean)*inv*gg0.x+bb0.x, (v0.y-mean)*inv*gg0.y+bb0.y);
        op[1] = __floats2bfloat162_rn((v0.z-mean)*inv*gg0.z+bb0.z, (v0.w-mean)*inv*gg0.w+bb0.w);
        op[2] = __floats2bfloat162_rn((v1.x-mean)*inv*gg1.x+bb1.x, (v1.y-mean)*inv*gg1.y+bb1.y);
        op[3] = __floats2bfloat162_rn((v1.z-mean)*inv*gg1.z+bb1.z, (v1.w-mean)*inv*gg1.w+bb1.w);
    }
}

// ---------------- generic bf16 GEMM (mma.sync m16n8k16) --------------
// C[M,N] = A[M,K] @ W[K,N] (+ epilogue).  BM=128, BN=128, BK=32, 256 thr.
// EPI: 0 = bf16 out + bias
//      1 = bf16 out + bias + exact GELU
//      2 = f32 out + bias + window-reverse scatter + shortcut add
//      3 = f32 out + bias + residual add (row-major)
#define GBM 128
#define GBN 128
#define GBK 32
#define GST 56     // smem row stride (elems): 112B -> 16B aligned, conflict-free frags

template<int EPI>
__global__ void __launch_bounds__(256) gemm_k(
    const bf16* __restrict__ A, const bf16* __restrict__ Wt,
    const float* __restrict__ bias, void* __restrict__ Cout,
    int M, int N, int K, const float* __restrict__ Xres) {

    __shared__ bf16 As[GBM*GST];
    __shared__ bf16 Bs[GBN*GST];

    int tid = threadIdx.x;
    int bm = blockIdx.y * GBM, bn = blockIdx.x * GBN;
    int warp = tid >> 5, lane = tid & 31;
    int wm = (warp & 3) * 32;     // 4 warps along M
    int wn = (warp >> 2) * 64;    // 2 warps along N
    int g = lane >> 2, t4 = lane & 3;

    float acc[2][8][4];
    #pragma unroll
    for (int mi = 0; mi < 2; mi++)
        #pragma unroll
        for (int ni = 0; ni < 8; ni++)
            acc[mi][ni][0]=acc[mi][ni][1]=acc[mi][ni][2]=acc[mi][ni][3]=0.f;

    for (int k0 = 0; k0 < K; k0 += GBK) {
        // A tile: 128x32 bf16, uint4 loads
        #pragma unroll
        for (int s = 0; s < 2; s++) {
            int l = tid + s*256;            // 0..511
            int row = l >> 2, col = (l & 3) * 8;
            uint4 v = *(const uint4*)(A + (size_t)(bm+row)*K + k0 + col);
            *(uint4*)(As + row*GST + col) = v;
        }
        // B tile: 32x128 transposed into Bs[n][k]
        #pragma unroll
        for (int s = 0; s < 16; s++) {
            int l = tid + s*256;            // 0..4095
            int kk = l >> 7, nn = l & 127;
            Bs[nn*GST + kk] = Wt[(size_t)(k0+kk)*N + bn + nn];
        }
        __syncthreads();

        #pragma unroll
        for (int kk = 0; kk < 2; kk++) {
            uint32_t af[2][4], bfr[8][2];
            #pragma unroll
            for (int mi = 0; mi < 2; mi++) {
                const bf16* ap = As + (wm + mi*16 + g)*GST + kk*16 + t4*2;
                af[mi][0] = *(const uint32_t*)(ap);
                af[mi][1] = *(const uint32_t*)(ap + 8*GST);
                af[mi][2] = *(const uint32_t*)(ap + 8);
                af[mi][3] = *(const uint32_t*)(ap + 8*GST + 8);
            }
            #pragma unroll
            for (int ni = 0; ni < 8; ni++) {
                const bf16* bp = Bs + (wn + ni*8 + g)*GST + kk*16 + t4*2;
                bfr[ni][0] = *(const uint32_t*)(bp);
                bfr[ni][1] = *(const uint32_t*)(bp + 8);
            }
            #pragma unroll
            for (int mi = 0; mi < 2; mi++)
                #pragma unroll
                for (int ni = 0; ni < 8; ni++)
                    mma16816(acc[mi][ni], af[mi], bfr[ni]);
        }
        __syncthreads();
    }

    // ---------------- epilogue ----------------
    #pragma unroll
    for (int mi = 0; mi < 2; mi++) {
        #pragma unroll
        for (int ni = 0; ni < 8; ni++) {
            int r0 = bm + wm + mi*16 + g;
            int cc = bn + wn + ni*8 + t4*2;
            float b0 = bias[cc], b1 = bias[cc+1];
            #pragma unroll
            for (int hr = 0; hr < 2; hr++) {
                int r = r0 + hr*8;
                float v0 = acc[mi][ni][hr*2+0] + b0;
                float v1 = acc[mi][ni][hr*2+1] + b1;
                if constexpr (EPI == 0) {
                    *(__nv_bfloat162*)((bf16*)Cout + (size_t)r*N + cc) =
                        __floats2bfloat162_rn(v0, v1);
                } else if constexpr (EPI == 1) {
                    v0 = v0 * normcdff(v0);
                    v1 = v1 * normcdff(v1);
                    *(__nv_bfloat162*)((bf16*)Cout + (size_t)r*N + cc) =
                        __floats2bfloat162_rn(v0, v1);
                } else if constexpr (EPI == 2) {
                    size_t dst = (size_t)winrow_to_orig(r) * CH + cc;
                    float2 sc = *(const float2*)(Xres + dst);
                    float2 o; o.x = v0 + sc.x; o.y = v1 + sc.y;
                    *(float2*)((float*)Cout + dst) = o;
                } else {  // EPI == 3
                    size_t dst = (size_t)r * CH + cc;
                    float2 sc = *(const float2*)(Xres + dst);
                    float2 o; o.x = v0 + sc.x; o.y = v1 + sc.y;
                    *(float2*)((float*)Cout + dst) = o;
                }
            }
        }
    }
}

// ---------------- fused windowed attention ----------------
// 1 CTA / window (256 thr = 8 warps). warps0-3: even heads strip-wise,
// warps4-7: odd heads. All mma.sync; softmax in registers.
#define QK_ST 264   // q/k smem stride (528B -> 4-bank row step, conflict-free)
#define VT_ST 72    // vT smem stride (144B -> 4-bank row step)
#define ATTN_SMEM (64*QK_ST*2*2 + 256*VT_ST*2 + 64*64*4 + 225*NHEAD*4)

__global__ void __launch_bounds__(256) attn_k(
    const bf16* __restrict__ q, const bf16* __restrict__ kv,
    const float* __restrict__ mask, const float* __restrict__ rel_table,
    bf16* __restrict__ ao) {

    extern __shared__ char smraw[];
    bf16*  qs   = (bf16*)smraw;
    bf16*  ks   = qs + 64*QK_ST;
    bf16*  vT   = ks + 64*QK_ST;
    float* msk  = (float*)(vT + 256*VT_ST);
    float* relb = msk + 64*64;

    int win = blockIdx.x;
    int winb = win & (NWIN-1);
    int tid = threadIdx.x, lane = tid & 31, warp = tid >> 5;

    // stage q (64x256), k (kv cols 0..255), vT (kv cols 256..511 transposed)
    const uint32_t* qg  = (const uint32_t*)(q  + (size_t)win*WTOK*CH);
    const uint32_t* kvg = (const uint32_t*)(kv + (size_t)win*WTOK*2*CH);
    #pragma unroll
    for (int s = 0; s < 32; s++) {
        int l = tid + s*256;            // 0..8191
        int row = l >> 7, col = l & 127;
        *(uint32_t*)(qs + row*QK_ST + col*2) = qg[row*128 + col];
        *(uint32_t*)(ks + row*QK_ST + col*2) = kvg[row*256 + col];
        uint32_t u = kvg[row*256 + 128 + col];
        __nv_bfloat162 uv = *reinterpret_cast<__nv_bfloat162*>(&u);
        vT[(2*col)  *VT_ST + row] = uv.x;
        vT[(2*col+1)*VT_ST + row] = uv.y;
    }
    const float* mg = mask + (size_t)winb*4096;
    for (int l = tid; l < 4096; l += 256) msk[l] = mg[l];
    for (int l = tid; l < 225*NHEAD; l += 256) relb[l] = rel_table[l];
    __syncthreads();

    int hgrp = warp >> 2;           // head parity
    int wg = warp & 3;
    int strip = wg * 16;
    int g = lane >> 2, t4 = lane & 3;
    int r0 = strip + g, r1 = r0 + 8;
    int ih0 = r0 >> 3, iw0 = r0 & 7, ih1 = r1 >> 3, iw1 = r1 & 7;

    for (int hp = 0; hp < 4; hp++) {
        int h = hp*2 + hgrp;
        int hc = h * HDIM;

        // ---- S = Q @ K^T  (M=16 strip, N=64, K=32) ----
        float sf[8][4];
        #pragma unroll
        for (int ni = 0; ni < 8; ni++)
            sf[ni][0]=sf[ni][1]=sf[ni][2]=sf[ni][3]=0.f;
        #pragma unroll
        for (int kk = 0; kk < 2; kk++) {
            uint32_t af[4];
            const bf16* ap = qs + r0*QK_ST + hc + kk*16 + t4*2;
            af[0] = *(const uint32_t*)(ap);
            af[1] = *(const uint32_t*)(ap + 8*QK_ST);
            af[2] = *(const uint32_t*)(ap + 8);
            af[3] = *(const uint32_t*)(ap + 8*QK_ST + 8);
            #pragma unroll
            for (int ni = 0; ni < 8; ni++) {
                const bf16* bp = ks + (ni*8 + g)*QK_ST + hc + kk*16 + t4*2;
                uint32_t bfr[2];
                bfr[0] = *(const uint32_t*)(bp);
                bfr[1] = *(const uint32_t*)(bp + 8);
                mma16816(sf[ni], af, bfr);
            }
        }

        // ---- scale + rel-pos bias + mask, row max ----
        float mx0 = -1e30f, mx1 = -1e30f;
        #pragma unroll
        for (int ni = 0; ni < 8; ni++) {
            #pragma unroll
            for (int e = 0; e < 2; e++) {
                int c = ni*8 + t4*2 + e;
                int jh = c >> 3, jw = c & 7;
                float bi0 = relb[((ih0-jh+7)*15 + (iw0-jw+7))*NHEAD + h];
                float bi1 = relb[((ih1-jh+7)*15 + (iw1-jw+7))*NHEAD + h];
                sf[ni][e]   = sf[ni][e]  *SCL + bi0 + msk[r0*64 + c];
                sf[ni][e+2] = sf[ni][e+2]*SCL + bi1 + msk[r1*64 + c];
                mx0 = fmaxf(mx0, sf[ni][e]);
                mx1 = fmaxf(mx1, sf[ni][e+2]);
            }
        }
        mx0 = fmaxf(mx0, __shfl_xor_sync(0xffffffffu, mx0, 1));
        mx0 = fmaxf(mx0, __shfl_xor_sync(0xffffffffu, mx0, 2));
        mx1 = fmaxf(mx1, __shfl_xor_sync(0xffffffffu, mx1, 1));
        mx1 = fmaxf(mx1, __shfl_xor_sync(0xffffffffu, mx1, 2));

        // ---- exp + row sum ----
        float sm0 = 0.f, sm1 = 0.f;
        #pragma unroll
        for (int ni = 0; ni < 8; ni++) {
            #pragma unroll
            for (int e = 0; e < 2; e++) {
                float e0 = __expf(sf[ni][e]   - mx0); sf[ni][e]   = e0; sm0 += e0;
                float e1 = __expf(sf[ni][e+2] - mx1); sf[ni][e+2] = e1; sm1 += e1;
            }
        }
        sm0 += __shfl_xor_sync(0xffffffffu, sm0, 1);
        sm0 += __shfl_xor_sync(0xffffffffu, sm0, 2);
        sm1 += __shfl_xor_sync(0xffffffffu, sm1, 1);
        sm1 += __shfl_xor_sync(0xffffffffu, sm1, 2);
        float inv0 = 1.f / sm0, inv1 = 1.f / sm1;

        // ---- O = P @ V  (M=16, N=32, K=64), P fragments straight from sf ----
        float of[4][4];
        #pragma unroll
        for (int di = 0; di < 4; di++)
            of[di][0]=of[di][1]=of[di][2]=of[di][3]=0.f;
        #pragma unroll
        for (int kt = 0; kt < 4; kt++) {
            uint32_t af2[4];
            af2[0] = pack_bf16(sf[2*kt][0],   sf[2*kt][1]);
            af2[1] = pack_bf16(sf[2*kt][2],   sf[2*kt][3]);
            af2[2] = pack_bf16(sf[2*kt+1][0], sf[2*kt+1][1]);
            af2[3] = pack_bf16(sf[2*kt+1][2], sf[2*kt+1][3]);
            #pragma unroll
            for (int di = 0; di < 4; di++) {
                const bf16* bp = vT + (hc + di*8 + g)*VT_ST + kt*16 + t4*2;
                uint32_t bfr[2];
                bfr[0] = *(const uint32_t*)(bp);
                bfr[1] = *(const uint32_t*)(bp + 8);
                mma16816(of[di], af2, bfr);
            }
        }

        // ---- store (normalize by row sum here) ----
        #pragma unroll
        for (int di = 0; di < 4; di++) {
            size_t o0 = ((size_t)win*WTOK + r0) * CH + hc + di*8 + t4*2;
            *(__nv_bfloat162*)(ao + o0) =
                __floats2bfloat162_rn(of[di][0]*inv0, of[di][1]*inv0);
            *(__nv_bfloat162*)(ao + o0 + 8*CH) =
                __floats2bfloat162_rn(of[di][2]*inv1, of[di][3]*inv1);
        }
    }
}

// ---------------- launcher ----------------
extern "C" void kernel_launch(void* const* d_in, const int* in_sizes, int n_in,
                              void* d_out, int out_size) {
    const float* ref     = (const float*)d_in[0];
    const float* adj     = (const float*)d_in[1];
    const float* mask    = (const float*)d_in[2];
    // d_in[3], d_in[4] = H, W (fixed 128)
    const float* n1g     = (const float*)d_in[5];
    const float* n1b     = (const float*)d_in[6];
    const float* q_w     = (const float*)d_in[7];
    const float* q_b     = (const float*)d_in[8];
    const float* kv_w    = (const float*)d_in[9];
    const float* kv_b    = (const float*)d_in[10];
    const float* rel_tab = (const float*)d_in[11];
    const float* proj_w  = (const float*)d_in[12];
    const float* proj_b  = (const float*)d_in[13];
    const float* n2g     = (const float*)d_in[14];
    const float* n2b     = (const float*)d_in[15];
    const float* fc1_w   = (const float*)d_in[16];
    const float* fc1_b   = (const float*)d_in[17];
    const float* fc2_w   = (const float*)d_in[18];
    const float* fc2_b   = (const float*)d_in[19];

    int B = in_sizes[0] / (LTOK * CH);
    int M = B * LTOK;                      // windowed rows == token rows

    bf16 *rw, *aw, *qb, *kvb, *aob, *xnb, *h1b;
    float *xb;
    bf16 *wq, *wkv, *wp, *w1, *w2;
    cudaGetSymbolAddress((void**)&rw,  g_rw);
    cudaGetSymbolAddress((void**)&aw,  g_aw);
    cudaGetSymbolAddress((void**)&qb,  g_q);
    cudaGetSymbolAddress((void**)&kvb, g_kv);
    cudaGetSymbolAddress((void**)&aob, g_ao);
    cudaGetSymbolAddress((void**)&xb,  g_x);
    cudaGetSymbolAddress((void**)&xnb, g_xn);
    cudaGetSymbolAddress((void**)&h1b, g_h1);
    cudaGetSymbolAddress((void**)&wq,  g_wq);
    cudaGetSymbolAddress((void**)&wkv, g_wkv);
    cudaGetSymbolAddress((void**)&wp,  g_wp);
    cudaGetSymbolAddress((void**)&w1,  g_w1);
    cudaGetSymbolAddress((void**)&w2,  g_w2);

    cudaFuncSetAttribute(attn_k, cudaFuncAttributeMaxDynamicSharedMemorySize, ATTN_SMEM);

    // 1. weights -> bf16
    cvt_weights_k<<<(CH*HID + 255)/256, 256>>>(q_w, kv_w, proj_w, fc1_w, fc2_w);

    // 2. LN1 + shift + window-partition gather (both ref and adj)
    ln_k<<<M/4, 128>>>(ref, adj, n1g, n1b, rw, aw, M, 1);

    // 3. Q and KV projections
    gemm_k<0><<<dim3(CH/GBN,   M/GBM), 256>>>(rw, wq,  q_b,  qb,  M, CH,   CH, nullptr);
    gemm_k<0><<<dim3(2*CH/GBN, M/GBM), 256>>>(aw, wkv, kv_b, kvb, M, 2*CH, CH, nullptr);

    // 4. fused windowed attention
    attn_k<<<B*NWIN, 256, ATTN_SMEM>>>(qb, kvb, mask, rel_tab, aob);

    // 5. proj GEMM + window-reverse + unshift + shortcut add  -> x (f32)
    gemm_k<2><<<dim3(CH/GBN, M/GBM), 256>>>(aob, wp, proj_b, xb, M, CH, CH, ref);

    // 6. LN2
    ln_k<<<M/4, 128>>>(xb, nullptr, n2g, n2b, xnb, nullptr, M, 0);

    // 7. MLP: fc1 + exact GELU, fc2 + residual -> d_out
    gemm_k<1><<<dim3(HID/GBN, M/GBM), 256>>>(xnb, w1, fc1_b, h1b, M, HID, CH, nullptr);
    gemm_k<3><<<dim3(CH/GBN,  M/GBM), 256>>>(h1b, w2, fc2_b, d_out, M, CH, HID, xb);
}

// round 14
// speedup vs baseline: 1.4282x; 1.4282x over previous
#include <cuda_runtime.h>
#include <cuda_bf16.h>
#include <cstdint>

typedef __nv_bfloat16 bf16;

// ---------------- problem dims (fixed by setup_inputs) ----------------
#define CH     256
#define NHEAD  8
#define HDIM   32
#define HSZ    128
#define WSZ    128
#define LTOK   16384
#define NWIN   256
#define WTOK   64
#define BMAX   8
#define HID    1024
#define SSHIFT 4
#define SCL    0.17677669529663687f

#define MROWS_MAX (BMAX*LTOK)

// ---------------- scratch (device globals; no allocation allowed) ----
__device__ bf16  g_rw[(size_t)MROWS_MAX*CH];
__device__ bf16  g_aw[(size_t)MROWS_MAX*CH];
__device__ bf16  g_q [(size_t)MROWS_MAX*CH];
__device__ bf16  g_kv[(size_t)MROWS_MAX*2*CH];
__device__ bf16  g_ao[(size_t)MROWS_MAX*CH];
__device__ float g_x [(size_t)MROWS_MAX*CH];
__device__ bf16  g_xn[(size_t)MROWS_MAX*CH];
__device__ bf16  g_h1[(size_t)MROWS_MAX*HID];
// weights stored TRANSPOSED: [N][K] row-major bf16
__device__ bf16  g_wq [CH*CH];
__device__ bf16  g_wkv[2*CH*CH];
__device__ bf16  g_wp [CH*CH];
__device__ bf16  g_w1 [HID*CH];
__device__ bf16  g_w2 [CH*HID];

// ---------------- helpers ----------------
__device__ __forceinline__ uint32_t smem_to_u32(const void* p) {
    uint32_t a;
    asm("{ .reg .u64 t; cvta.to.shared.u64 t, %1; cvt.u32.u64 %0, t; }" : "=r"(a) : "l"(p));
    return a;
}
__device__ __forceinline__ void mma16816(float* d, const uint32_t* a, const uint32_t* b) {
    asm volatile(
        "mma.sync.aligned.m16n8k16.row.col.f32.bf16.bf16.f32 "
        "{%0,%1,%2,%3}, {%4,%5,%6,%7}, {%8,%9}, {%0,%1,%2,%3};\n"
        : "+f"(d[0]), "+f"(d[1]), "+f"(d[2]), "+f"(d[3])
        : "r"(a[0]), "r"(a[1]), "r"(a[2]), "r"(a[3]), "r"(b[0]), "r"(b[1]));
}
__device__ __forceinline__ uint32_t pack_bf16(float x, float y) {
    __nv_bfloat162 t = __floats2bfloat162_rn(x, y);
    return *reinterpret_cast<uint32_t*>(&t);
}

// windowed row -> original (b,l) row  (win-reverse + roll(+SS))
__device__ __forceinline__ int winrow_to_orig(int r) {
    int b = r >> 14;
    int rem = r & 16383;
    int win = rem >> 6, n = rem & 63;
    int wh = win >> 4, ww = win & 15;
    int ih = n >> 3,  iw = n & 7;
    int h0 = (wh*8 + ih + SSHIFT) & (HSZ-1);
    int w0 = (ww*8 + iw + SSHIFT) & (WSZ-1);
    return (b << 14) + (h0 << 7) + w0;
}

// ---------------- weight transpose fp32[K][N] -> bf16[N][K] ----------
__global__ void transpose_w_k(const float* __restrict__ src, bf16* __restrict__ dst,
                              int K, int N) {
    __shared__ float t[32][33];
    int kb = blockIdx.y*32, nb = blockIdx.x*32;
    int tx = threadIdx.x, ty = threadIdx.y;      // 32 x 8
    #pragma unroll
    for (int i = 0; i < 32; i += 8)
        t[ty+i][tx] = src[(size_t)(kb+ty+i)*N + nb+tx];
    __syncthreads();
    #pragma unroll
    for (int i = 0; i < 32; i += 8)
        dst[(size_t)(nb+ty+i)*K + kb+tx] = __float2bfloat16(t[tx][ty+i]);
}

// ---------------- LayerNorm (+ optional shift/window gather) ----------
__global__ void ln_k(const float* __restrict__ in0, const float* __restrict__ in1,
                     const float* __restrict__ gam, const float* __restrict__ bet,
                     bf16* __restrict__ out0, bf16* __restrict__ out1,
                     int nrows, int gather) {
    int gw = (blockIdx.x * blockDim.x + threadIdx.x) >> 5;
    if (gw >= nrows) return;
    int lane = threadIdx.x & 31;

    size_t src;
    if (gather) src = (size_t)winrow_to_orig(gw) * CH;
    else        src = (size_t)gw * CH;
    size_t dst = (size_t)gw * CH;

    float4 gg0 = *(const float4*)(gam + lane*8);
    float4 gg1 = *(const float4*)(gam + lane*8 + 4);
    float4 bb0 = *(const float4*)(bet + lane*8);
    float4 bb1 = *(const float4*)(bet + lane*8 + 4);

    for (int t = 0; t < 2; t++) {
        const float* in  = (t == 0) ? in0  : in1;
        bf16*        out = (t == 0) ? out0 : out1;
        if (in == nullptr) break;

        float4 v0 = *(const float4*)(in + src + lane*8);
        float4 v1 = *(const float4*)(in + src + lane*8 + 4);
        float s  = v0.x+v0.y+v0.z+v0.w + v1.x+v1.y+v1.z+v1.w;
        float q  = v0.x*v0.x+v0.y*v0.y+v0.z*v0.z+v0.w*v0.w
                 + v1.x*v1.x+v1.y*v1.y+v1.z*v1.z+v1.w*v1.w;
        #pragma unroll
        for (int o = 16; o; o >>= 1) {
            s += __shfl_xor_sync(0xffffffffu, s, o);
            q += __shfl_xor_sync(0xffffffffu, q, o);
        }
        float mean = s * (1.f/CH);
        float var  = q * (1.f/CH) - mean*mean;
        float inv  = rsqrtf(var + 1e-5f);

        __nv_bfloat162* op = (__nv_bfloat162*)(out + dst + lane*8);
        op[0] = __floats2bfloat162_rn((v0.x-mean)*inv*gg0.x+bb0.x, (v0.y-mean)*inv*gg0.y+bb0.y);
        op[1] = __floats2bfloat162_rn((v0.z-mean)*inv*gg0.z+bb0.z, (v0.w-mean)*inv*gg0.w+bb0.w);
        op[2] = __floats2bfloat162_rn((v1.x-mean)*inv*gg1.x+bb1.x, (v1.y-mean)*inv*gg1.y+bb1.y);
        op[3] = __floats2bfloat162_rn((v1.z-mean)*inv*gg1.z+bb1.z, (v1.w-mean)*inv*gg1.w+bb1.w);
    }
}

// ---------------- bf16 GEMM (mma.sync), 2-stage cp.async pipeline ----
// C[M,N] = A[M,K] @ W[K,N], W pre-transposed as Wt[N][K].
// BM=128, BN=64, BK=32, 256 thr (8 warps, 4Mx2N, warp tile 32x32).
// 2 CTAs/SM via __launch_bounds__(256,2).
// EPI: 0 bf16+bias | 1 bf16+bias+GELU | 2 f32+bias+winrev+res | 3 f32+bias+res
#define GBM 128
#define GBN 64
#define GBK 32
#define GST 56                      // row stride (elems) = 112B, conflict-free frags
#define STG ((GBM+GBN)*GST)         // elems per pipeline stage

__device__ __forceinline__ void g5_load_stage(
    int stage, const bf16* A, const bf16* Wt, bf16* smbase,
    int bm, int bn, int K, int k0, int tid) {
    #pragma unroll
    for (int s = 0; s < 3; s++) {
        int l = tid + s*256;            // 0..767, 16B copies
        const bf16* gp;
        bf16* dp;
        if (l < 512) {                  // A: 128 rows x 4 copies
            int row = l >> 2, cc = l & 3;
            gp = A + (size_t)(bm+row)*K + k0 + cc*8;
            dp = smbase + stage*STG + row*GST + cc*8;
        } else {                        // B: 64 rows x 4 copies
            int l2 = l - 512;
            int row = l2 >> 2, cc = l2 & 3;
            gp = Wt + (size_t)(bn+row)*K + k0 + cc*8;
            dp = smbase + stage*STG + GBM*GST + row*GST + cc*8;
        }
        uint32_t sp = smem_to_u32(dp);
        asm volatile("cp.async.cg.shared.global [%0], [%1], 16;\n" :: "r"(sp), "l"(gp));
    }
    asm volatile("cp.async.commit_group;\n" ::: "memory");
}

template<int EPI>
__global__ void __launch_bounds__(256, 2) gemm_k(
    const bf16* __restrict__ A, const bf16* __restrict__ Wt,
    const float* __restrict__ bias, void* __restrict__ Cout,
    int M, int N, int K, const float* __restrict__ Xres) {

    __shared__ bf16 sm[2*STG];
    __shared__ float bias_s[GBN];

    int tid = threadIdx.x;
    int bm = blockIdx.y * GBM, bn = blockIdx.x * GBN;
    int warp = tid >> 5, lane = tid & 31;
    int wm = (warp & 3) * 32;           // 4 warps along M
    int wn = (warp >> 2) * 32;          // 2 warps along N
    int g = lane >> 2, t4 = lane & 3;

    if (tid < 16) *(float4*)(bias_s + tid*4) = *(const float4*)(bias + bn + tid*4);

    float acc[2][4][4];
    #pragma unroll
    for (int mi = 0; mi < 2; mi++)
        #pragma unroll
        for (int ni = 0; ni < 4; ni++)
            acc[mi][ni][0]=acc[mi][ni][1]=acc[mi][ni][2]=acc[mi][ni][3]=0.f;

    int nchunk = K / GBK;
    g5_load_stage(0, A, Wt, sm, bm, bn, K, 0, tid);

    for (int c = 0; c < nchunk; c++) {
        if (c + 1 < nchunk) {
            g5_load_stage((c+1)&1, A, Wt, sm, bm, bn, K, (c+1)*GBK, tid);
            asm volatile("cp.async.wait_group 1;\n" ::: "memory");
        } else {
            asm volatile("cp.async.wait_group 0;\n" ::: "memory");
        }
        __syncthreads();

        const bf16* As = sm + (c&1)*STG;
        const bf16* Bs = As + GBM*GST;
        #pragma unroll
        for (int kk = 0; kk < 2; kk++) {
            uint32_t af[2][4], bfr[4][2];
            #pragma unroll
            for (int mi = 0; mi < 2; mi++) {
                const bf16* ap = As + (wm + mi*16 + g)*GST + kk*16 + t4*2;
                af[mi][0] = *(const uint32_t*)(ap);
                af[mi][1] = *(const uint32_t*)(ap + 8*GST);
                af[mi][2] = *(const uint32_t*)(ap + 8);
                af[mi][3] = *(const uint32_t*)(ap + 8*GST + 8);
            }
            #pragma unroll
            for (int ni = 0; ni < 4; ni++) {
                const bf16* bp = Bs + (wn + ni*8 + g)*GST + kk*16 + t4*2;
                bfr[ni][0] = *(const uint32_t*)(bp);
                bfr[ni][1] = *(const uint32_t*)(bp + 8);
            }
            #pragma unroll
            for (int mi = 0; mi < 2; mi++)
                #pragma unroll
                for (int ni = 0; ni < 4; ni++)
                    mma16816(acc[mi][ni], af[mi], bfr[ni]);
        }
        __syncthreads();
    }

    // ---------------- epilogue ----------------
    #pragma unroll
    for (int mi = 0; mi < 2; mi++) {
        #pragma unroll
        for (int ni = 0; ni < 4; ni++) {
            int r0 = bm + wm + mi*16 + g;
            int lc = wn + ni*8 + t4*2;          // local col 0..63
            int cc = bn + lc;
            float b0 = bias_s[lc], b1 = bias_s[lc+1];
            #pragma unroll
            for (int hr = 0; hr < 2; hr++) {
                int r = r0 + hr*8;
                float v0 = acc[mi][ni][hr*2+0] + b0;
                float v1 = acc[mi][ni][hr*2+1] + b1;
                if constexpr (EPI == 0) {
                    *(__nv_bfloat162*)((bf16*)Cout + (size_t)r*N + cc) =
                        __floats2bfloat162_rn(v0, v1);
                } else if constexpr (EPI == 1) {
                    v0 = v0 * normcdff(v0);
                    v1 = v1 * normcdff(v1);
                    *(__nv_bfloat162*)((bf16*)Cout + (size_t)r*N + cc) =
                        __floats2bfloat162_rn(v0, v1);
                } else if constexpr (EPI == 2) {
                    size_t dst = (size_t)winrow_to_orig(r) * CH + cc;
                    float2 sc = *(const float2*)(Xres + dst);
                    float2 o; o.x = v0 + sc.x; o.y = v1 + sc.y;
                    *(float2*)((float*)Cout + dst) = o;
                } else {  // EPI == 3
                    size_t dst = (size_t)r * CH + cc;
                    float2 sc = *(const float2*)(Xres + dst);
                    float2 o; o.x = v0 + sc.x; o.y = v1 + sc.y;
                    *(float2*)((float*)Cout + dst) = o;
                }
            }
        }
    }
}

// ---------------- fused windowed attention (unchanged, passed R1) ----
#define QK_ST 264
#define VT_ST 72
#define ATTN_SMEM (64*QK_ST*2*2 + 256*VT_ST*2 + 64*64*4 + 225*NHEAD*4)

__global__ void __launch_bounds__(256) attn_k(
    const bf16* __restrict__ q, const bf16* __restrict__ kv,
    const float* __restrict__ mask, const float* __restrict__ rel_table,
    bf16* __restrict__ ao) {

    extern __shared__ char smraw[];
    bf16*  qs   = (bf16*)smraw;
    bf16*  ks   = qs + 64*QK_ST;
    bf16*  vT   = ks + 64*QK_ST;
    float* msk  = (float*)(vT + 256*VT_ST);
    float* relb = msk + 64*64;

    int win = blockIdx.x;
    int winb = win & (NWIN-1);
    int tid = threadIdx.x, lane = tid & 31, warp = tid >> 5;

    const uint32_t* qg  = (const uint32_t*)(q  + (size_t)win*WTOK*CH);
    const uint32_t* kvg = (const uint32_t*)(kv + (size_t)win*WTOK*2*CH);
    #pragma unroll
    for (int s = 0; s < 32; s++) {
        int l = tid + s*256;
        int row = l >> 7, col = l & 127;
        *(uint32_t*)(qs + row*QK_ST + col*2) = qg[row*128 + col];
        *(uint32_t*)(ks + row*QK_ST + col*2) = kvg[row*256 + col];
        uint32_t u = kvg[row*256 + 128 + col];
        __nv_bfloat162 uv = *reinterpret_cast<__nv_bfloat162*>(&u);
        vT[(2*col)  *VT_ST + row] = uv.x;
        vT[(2*col+1)*VT_ST + row] = uv.y;
    }
    const float* mg = mask + (size_t)winb*4096;
    for (int l = tid; l < 4096; l += 256) msk[l] = mg[l];
    for (int l = tid; l < 225*NHEAD; l += 256) relb[l] = rel_table[l];
    __syncthreads();

    int hgrp = warp >> 2;
    int wg = warp & 3;
    int strip = wg * 16;
    int g = lane >> 2, t4 = lane & 3;
    int r0 = strip + g, r1 = r0 + 8;
    int ih0 = r0 >> 3, iw0 = r0 & 7, ih1 = r1 >> 3, iw1 = r1 & 7;

    for (int hp = 0; hp < 4; hp++) {
        int h = hp*2 + hgrp;
        int hc = h * HDIM;

        float sf[8][4];
        #pragma unroll
        for (int ni = 0; ni < 8; ni++)
            sf[ni][0]=sf[ni][1]=sf[ni][2]=sf[ni][3]=0.f;
        #pragma unroll
        for (int kk = 0; kk < 2; kk++) {
            uint32_t af[4];
            const bf16* ap = qs + r0*QK_ST + hc + kk*16 + t4*2;
            af[0] = *(const uint32_t*)(ap);
            af[1] = *(const uint32_t*)(ap + 8*QK_ST);
            af[2] = *(const uint32_t*)(ap + 8);
            af[3] = *(const uint32_t*)(ap + 8*QK_ST + 8);
            #pragma unroll
            for (int ni = 0; ni < 8; ni++) {
                const bf16* bp = ks + (ni*8 + g)*QK_ST + hc + kk*16 + t4*2;
                uint32_t bfr[2];
                bfr[0] = *(const uint32_t*)(bp);
                bfr[1] = *(const uint32_t*)(bp + 8);
                mma16816(sf[ni], af, bfr);
            }
        }

        float mx0 = -1e30f, mx1 = -1e30f;
        #pragma unroll
        for (int ni = 0; ni < 8; ni++) {
            #pragma unroll
            for (int e = 0; e < 2; e++) {
                int c = ni*8 + t4*2 + e;
                int jh = c >> 3, jw = c & 7;
                float bi0 = relb[((ih0-jh+7)*15 + (iw0-jw+7))*NHEAD + h];
                float bi1 = relb[((ih1-jh+7)*15 + (iw1-jw+7))*NHEAD + h];
                sf[ni][e]   = sf[ni][e]  *SCL + bi0 + msk[r0*64 + c];
                sf[ni][e+2] = sf[ni][e+2]*SCL + bi1 + msk[r1*64 + c];
                mx0 = fmaxf(mx0, sf[ni][e]);
                mx1 = fmaxf(mx1, sf[ni][e+2]);
            }
        }
        mx0 = fmaxf(mx0, __shfl_xor_sync(0xffffffffu, mx0, 1));
        mx0 = fmaxf(mx0, __shfl_xor_sync(0xffffffffu, mx0, 2));
        mx1 = fmaxf(mx1, __shfl_xor_sync(0xffffffffu, mx1, 1));
        mx1 = fmaxf(mx1, __shfl_xor_sync(0xffffffffu, mx1, 2));

        float sm0 = 0.f, sm1 = 0.f;
        #pragma unroll
        for (int ni = 0; ni < 8; ni++) {
            #pragma unroll
            for (int e = 0; e < 2; e++) {
                float e0 = __expf(sf[ni][e]   - mx0); sf[ni][e]   = e0; sm0 += e0;
                float e1 = __expf(sf[ni][e+2] - mx1); sf[ni][e+2] = e1; sm1 += e1;
            }
        }
        sm0 += __shfl_xor_sync(0xffffffffu, sm0, 1);
        sm0 += __shfl_xor_sync(0xffffffffu, sm0, 2);
        sm1 += __shfl_xor_sync(0xffffffffu, sm1, 1);
        sm1 += __shfl_xor_sync(0xffffffffu, sm1, 2);
        float inv0 = 1.f / sm0, inv1 = 1.f / sm1;

        float of[4][4];
        #pragma unroll
        for (int di = 0; di < 4; di++)
            of[di][0]=of[di][1]=of[di][2]=of[di][3]=0.f;
        #pragma unroll
        for (int kt = 0; kt < 4; kt++) {
            uint32_t af2[4];
            af2[0] = pack_bf16(sf[2*kt][0],   sf[2*kt][1]);
            af2[1] = pack_bf16(sf[2*kt][2],   sf[2*kt][3]);
            af2[2] = pack_bf16(sf[2*kt+1][0], sf[2*kt+1][1]);
            af2[3] = pack_bf16(sf[2*kt+1][2], sf[2*kt+1][3]);
            #pragma unroll
            for (int di = 0; di < 4; di++) {
                const bf16* bp = vT + (hc + di*8 + g)*VT_ST + kt*16 + t4*2;
                uint32_t bfr[2];
                bfr[0] = *(const uint32_t*)(bp);
                bfr[1] = *(const uint32_t*)(bp + 8);
                mma16816(of[di], af2, bfr);
            }
        }

        #pragma unroll
        for (int di = 0; di < 4; di++) {
            size_t o0 = ((size_t)win*WTOK + r0) * CH + hc + di*8 + t4*2;
            *(__nv_bfloat162*)(ao + o0) =
                __floats2bfloat162_rn(of[di][0]*inv0, of[di][1]*inv0);
            *(__nv_bfloat162*)(ao + o0 + 8*CH) =
                __floats2bfloat162_rn(of[di][2]*inv1, of[di][3]*inv1);
        }
    }
}

// ---------------- launcher ----------------
extern "C" void kernel_launch(void* const* d_in, const int* in_sizes, int n_in,
                              void* d_out, int out_size) {
    const float* ref     = (const float*)d_in[0];
    const float* adj     = (const float*)d_in[1];
    const float* mask    = (const float*)d_in[2];
    const float* n1g     = (const float*)d_in[5];
    const float* n1b     = (const float*)d_in[6];
    const float* q_w     = (const float*)d_in[7];
    const float* q_b     = (const float*)d_in[8];
    const float* kv_w    = (const float*)d_in[9];
    const float* kv_b    = (const float*)d_in[10];
    const float* rel_tab = (const float*)d_in[11];
    const float* proj_w  = (const float*)d_in[12];
    const float* proj_b  = (const float*)d_in[13];
    const float* n2g     = (const float*)d_in[14];
    const float* n2b     = (const float*)d_in[15];
    const float* fc1_w   = (const float*)d_in[16];
    const float* fc1_b   = (const float*)d_in[17];
    const float* fc2_w   = (const float*)d_in[18];
    const float* fc2_b   = (const float*)d_in[19];

    int B = in_sizes[0] / (LTOK * CH);
    int M = B * LTOK;

    bf16 *rw, *aw, *qb, *kvb, *aob, *xnb, *h1b;
    float *xb;
    bf16 *wq, *wkv, *wp, *w1, *w2;
    cudaGetSymbolAddress((void**)&rw,  g_rw);
    cudaGetSymbolAddress((void**)&aw,  g_aw);
    cudaGetSymbolAddress((void**)&qb,  g_q);
    cudaGetSymbolAddress((void**)&kvb, g_kv);
    cudaGetSymbolAddress((void**)&aob, g_ao);
    cudaGetSymbolAddress((void**)&xb,  g_x);
    cudaGetSymbolAddress((void**)&xnb, g_xn);
    cudaGetSymbolAddress((void**)&h1b, g_h1);
    cudaGetSymbolAddress((void**)&wq,  g_wq);
    cudaGetSymbolAddress((void**)&wkv, g_wkv);
    cudaGetSymbolAddress((void**)&wp,  g_wp);
    cudaGetSymbolAddress((void**)&w1,  g_w1);
    cudaGetSymbolAddress((void**)&w2,  g_w2);

    cudaFuncSetAttribute(attn_k, cudaFuncAttributeMaxDynamicSharedMemorySize, ATTN_SMEM);

    // 1. weights -> bf16 transposed [N][K]
    transpose_w_k<<<dim3(CH/32,  CH/32),  dim3(32,8)>>>(q_w,    wq,  CH,  CH);
    transpose_w_k<<<dim3(2*CH/32,CH/32),  dim3(32,8)>>>(kv_w,   wkv, CH,  2*CH);
    transpose_w_k<<<dim3(CH/32,  CH/32),  dim3(32,8)>>>(proj_w, wp,  CH,  CH);
    transpose_w_k<<<dim3(HID/32, CH/32),  dim3(32,8)>>>(fc1_w,  w1,  CH,  HID);
    transpose_w_k<<<dim3(CH/32,  HID/32), dim3(32,8)>>>(fc2_w,  w2,  HID, CH);

    // 2. LN1 + shift + window-partition gather (ref and adj)
    ln_k<<<M/4, 128>>>(ref, adj, n1g, n1b, rw, aw, M, 1);

    // 3. Q and KV projections
    gemm_k<0><<<dim3(CH/GBN,   M/GBM), 256>>>(rw, wq,  q_b,  qb,  M, CH,   CH, nullptr);
    gemm_k<0><<<dim3(2*CH/GBN, M/GBM), 256>>>(aw, wkv, kv_b, kvb, M, 2*CH, CH, nullptr);

    // 4. fused windowed attention
    attn_k<<<B*NWIN, 256, ATTN_SMEM>>>(qb, kvb, mask, rel_tab, aob);

    // 5. proj + window-reverse + unshift + shortcut add -> x (f32)
    gemm_k<2><<<dim3(CH/GBN, M/GBM), 256>>>(aob, wp, proj_b, xb, M, CH, CH, ref);

    // 6. LN2
    ln_k<<<M/4, 128>>>(xb, nullptr, n2g, n2b, xnb, nullptr, M, 0);

    // 7. MLP: fc1 + exact GELU, fc2 + residual -> d_out
    gemm_k<1><<<dim3(HID/GBN, M/GBM), 256>>>(xnb, w1, fc1_b, h1b, M, HID, CH, nullptr);
    gemm_k<3><<<dim3(CH/GBN,  M/GBM), 256>>>(h1b, w2, fc2_b, d_out, M, CH, HID, xb);
}